// round 4
// baseline (speedup 1.0000x reference)
#include <cuda_runtime.h>
#include <cuda_bf16.h>

#define NMAT 512
#define N2   (NMAT * NMAT)
#define RPB  8
#define NB   (NMAT / RPB)   // 64 blocks

__device__ float  g_F[N2];        // exp-domain FW state
__device__ float  g_row[N2];      // write-once row broadcast, sentinel -1
__device__ double g_part[NB * 4]; // per-block partial sums

static __device__ __forceinline__ float ld_acq(const float* p) {
    unsigned v;
    asm volatile("ld.acquire.gpu.global.b32 %0, [%1];" : "=r"(v) : "l"(p) : "memory");
    return __uint_as_float(v);
}
static __device__ __forceinline__ void st_rel(float* p, float v) {
    asm volatile("st.release.gpu.global.b32 [%0], %1;" :: "l"(p), "r"(__float_as_uint(v)) : "memory");
}

// ---------------- init: F = exp(40 - 10*w0), w0 = dist/(soft+1e-4), diag 0; sentinels
__global__ void init_kernel(const float* __restrict__ sa, const float* __restrict__ dist) {
    int idx = blockIdx.x * blockDim.x + threadIdx.x;
    int i = idx >> 9, j = idx & (NMAT - 1);
    float w = (i == j) ? 0.0f : dist[idx] / (sa[idx] + 1e-4f);
    g_F[idx]   = __expf(fmaf(-10.0f, w, 40.0f));   // underflows to 0 for huge w (== +inf path)
    g_row[idx] = -1.0f;
}

// one FW step applied to this block's 8 register-resident rows
static __device__ __forceinline__ void step_update(float (&f)[RPB], float* stg,
                                                   float fkj, bool writer) {
    const float CINV = 4.248354255291589e-18f;   // exp(-40)
    if (writer) {
        ((float4*)stg)[0] = make_float4(f[0]*CINV, f[1]*CINV, f[2]*CINV, f[3]*CINV);
        ((float4*)stg)[1] = make_float4(f[4]*CINV, f[5]*CINV, f[6]*CINV, f[7]*CINV);
    }
    __syncthreads();
    float4 c0 = ((const float4*)stg)[0];
    float4 c1 = ((const float4*)stg)[1];
    f[0] = fmaf(c0.x, fkj, f[0]);  f[1] = fmaf(c0.y, fkj, f[1]);
    f[2] = fmaf(c0.z, fkj, f[2]);  f[3] = fmaf(c0.w, fkj, f[3]);
    f[4] = fmaf(c1.x, fkj, f[4]);  f[5] = fmaf(c1.y, fkj, f[5]);
    f[6] = fmaf(c1.z, fkj, f[6]);  f[7] = fmaf(c1.w, fkj, f[7]);
}

// ---------------- persistent pipelined exp-domain Floyd-Warshall + fused loss tail
__global__ void __launch_bounds__(NMAT, 1) fw_kernel(const float* __restrict__ sa,
                                                     const float* __restrict__ oa,
                                                     const float* __restrict__ dist,
                                                     const float* __restrict__ flow) {
    const int tid  = threadIdx.x;
    const int b    = blockIdx.x;
    const int base = b * RPB;

    float f[RPB];                              // f[r] = F[base+r][tid]
#pragma unroll
    for (int r = 0; r < RPB; r++) f[r] = g_F[(base + r) * NMAT + tid];

    __shared__ __align__(16) float stage[2][RPB];

    for (int c = 0; c < NB; c++) {
        const int k0 = c * RPB;
        if (c == b) {
            // producer: publish pre-step row values, then update own rows
#pragma unroll
            for (int j = 0; j < RPB; j++) {
                const int k = k0 + j;
                const float fkj = f[j];                 // F[k][tid] with steps 0..k-1 applied
                st_rel(&g_row[k * NMAT + tid], fkj);
                step_update(f, stage[j & 1], fkj, tid == k);
            }
        } else {
            // consumer: probe LAST row of the chunk; release/acquire pairs are per
            // (producer thread t -> consumer thread t, same column), so seeing it
            // implies rows k0..k0+7 of this column are visible.
            float probe = ld_acq(&g_row[(k0 + RPB - 1) * NMAT + tid]);
            if (__syncthreads_and(probe != -1.0f)) {
                float rr[RPB];
#pragma unroll
                for (int j = 0; j < RPB - 1; j++) rr[j] = g_row[(k0 + j) * NMAT + tid];
                rr[RPB - 1] = probe;
#pragma unroll
                for (int j = 0; j < RPB; j++)
                    step_update(f, stage[j & 1], rr[j], tid == (k0 + j));
            } else {
#pragma unroll
                for (int j = 0; j < RPB; j++) {
                    const int k = k0 + j;
                    float fkj = (j == RPB - 1) ? probe : ld_acq(&g_row[k * NMAT + tid]);
                    while (fkj == -1.0f) { __nanosleep(64); fkj = ld_acq(&g_row[k * NMAT + tid]); }
                    step_update(f, stage[j & 1], fkj, tid == k);
                }
            }
        }
    }

    // ---- fused elementwise loss + reduction over this block's 8 rows (F in regs)
    double s_cost = 0.0, s_util = 0.0, s_ent = 0.0, s_mask = 0.0;
#pragma unroll
    for (int r = 0; r < RPB; r++) {
        int idx = (base + r) * NMAT + tid;
        float s  = sa[idx];
        float d  = dist[idx];
        float fl = flow[idx];
        float o  = oa[idx];

        s_cost += (double)(s * d);
        float eye = (base + r == tid) ? 1.0f : 0.0f;
        float t   = s * (eye - s);
        s_ent  += (double)(t * t);
        s_mask += (double)(s * (1.0f - o));

        float F  = f[r];
        float sp = (F > 1e-37f) ? fmaf(-0.1f, __logf(F), 4.0f) : 1.0e6f;  // w = 4 - 0.1*lnF
        float rail   = __expf(-0.005f * sp);      // exp(-0.01 * 0.5 * sp)
        float bas    = __expf(-0.01f  * d);
        float choice = rail / (rail + bas);
        float saved  = fmaf(-0.5f, sp, d);
        float u      = fl * choice * saved;
        float elu    = (u > 0.0f) ? u : expm1f(u);
        s_util += (double)(elu + 1.0f);
    }

    // deterministic block reduce: warp shuffle -> smem -> thread 0
    const unsigned FULL = 0xffffffffu;
#pragma unroll
    for (int off = 16; off > 0; off >>= 1) {
        s_cost += __shfl_down_sync(FULL, s_cost, off);
        s_util += __shfl_down_sync(FULL, s_util, off);
        s_ent  += __shfl_down_sync(FULL, s_ent , off);
        s_mask += __shfl_down_sync(FULL, s_mask, off);
    }
    __shared__ double red[16][4];
    int wid = tid >> 5, lid = tid & 31;
    if (lid == 0) { red[wid][0]=s_cost; red[wid][1]=s_util; red[wid][2]=s_ent; red[wid][3]=s_mask; }
    __syncthreads();
    if (tid == 0) {
        double a0=0, a1=0, a2=0, a3=0;
#pragma unroll
        for (int w = 0; w < 16; w++) { a0+=red[w][0]; a1+=red[w][1]; a2+=red[w][2]; a3+=red[w][3]; }
        g_part[b*4+0]=a0; g_part[b*4+1]=a1; g_part[b*4+2]=a2; g_part[b*4+3]=a3;
    }
}

// ---------------- final: sum 64 partials, apply entropy scale, write scalar
__global__ void final_kernel(const int* __restrict__ epoch_p, float* __restrict__ out) {
    int t = threadIdx.x;   // 32 threads
    double c0 = g_part[t*4+0] + g_part[(t+32)*4+0];
    double c1 = g_part[t*4+1] + g_part[(t+32)*4+1];
    double c2 = g_part[t*4+2] + g_part[(t+32)*4+2];
    double c3 = g_part[t*4+3] + g_part[(t+32)*4+3];
    const unsigned FULL = 0xffffffffu;
#pragma unroll
    for (int off = 16; off > 0; off >>= 1) {
        c0 += __shfl_down_sync(FULL, c0, off);
        c1 += __shfl_down_sync(FULL, c1, off);
        c2 += __shfl_down_sync(FULL, c2, off);
        c3 += __shfl_down_sync(FULL, c3, off);
    }
    if (t == 0) {
        int e = *epoch_p;
        // bisect([0,10,50], e) -> ENTROPY_LEVELS[0.0, 0.05, 0.1, 1.0]
        double es = (e >= 50) ? 1.0 : (e >= 10) ? 0.1 : (e >= 0) ? 0.05 : 0.0;
        out[0] = (float)(c0 + c1 + c2 * es + 10000.0 * c3);
    }
}

extern "C" void kernel_launch(void* const* d_in, const int* in_sizes, int n_in,
                              void* d_out, int out_size) {
    const float* sa   = (const float*)d_in[0];   // soft_adj
    const float* oa   = (const float*)d_in[1];   // original_adj
    const float* dist = (const float*)d_in[2];   // distances
    const float* flow = (const float*)d_in[3];   // flow
    const int*   ep   = (const int*)  d_in[4];   // epoch

    init_kernel<<<N2 / 512, 512>>>(sa, dist);
    fw_kernel<<<NB, NMAT>>>(sa, oa, dist, flow);
    final_kernel<<<1, 32>>>(ep, (float*)d_out);
}

// round 5
// speedup vs baseline: 1.4811x; 1.4811x over previous
#include <cuda_runtime.h>
#include <cuda_bf16.h>

#define NMAT 512
#define N2   (NMAT * NMAT)
#define RPB  8
#define NB   (NMAT / RPB)   // 64 blocks / chunks

__device__ float    g_F[N2];        // exp-domain FW state (init only; fw keeps rows in regs)
__device__ float    g_B[N2];        // published scaled rows: B~[k][j] = CINV * (row k at time k)
__device__ unsigned g_flag[NB];     // per-chunk publish flag
__device__ double   g_part[NB * 4]; // per-block partial sums

#define CINV 4.248354255291589e-18f  /* exp(-40) */

static __device__ __forceinline__ unsigned ld_acq_u(const unsigned* p) {
    unsigned v;
    asm volatile("ld.acquire.gpu.global.b32 %0, [%1];" : "=r"(v) : "l"(p) : "memory");
    return v;
}
static __device__ __forceinline__ void st_rel_u(unsigned* p, unsigned v) {
    asm volatile("st.release.gpu.global.b32 [%0], %1;" :: "l"(p), "r"(v) : "memory");
}

// ---------------- init: F = exp(40 - 10*w0), w0 = dist/(soft+1e-4), diag 0; flags = 0
__global__ void init_kernel(const float* __restrict__ sa, const float* __restrict__ dist) {
    int idx = blockIdx.x * blockDim.x + threadIdx.x;
    int i = idx >> 9, j = idx & (NMAT - 1);
    float w = (i == j) ? 0.0f : dist[idx] / (sa[idx] + 1e-4f);
    g_F[idx] = __expf(fmaf(-10.0f, w, 40.0f));
    if (idx < NB) g_flag[idx] = 0u;
}

// ---------------- persistent blocked exp-domain Floyd-Warshall (rank-8 per chunk) + fused loss
__global__ void __launch_bounds__(NMAT, 1) fw_kernel(const float* __restrict__ sa,
                                                     const float* __restrict__ oa,
                                                     const float* __restrict__ dist,
                                                     const float* __restrict__ flow) {
    const int tid  = threadIdx.x;
    const int b    = blockIdx.x;
    const int base = b * RPB;

    float f[RPB];                              // f[r] = F[base+r][tid]
#pragma unroll
    for (int r = 0; r < RPB; r++) f[r] = g_F[(base + r) * NMAT + tid];

    __shared__ float s_c0[RPB][RPB];   // own rows at chunk columns (chunk-start)
    __shared__ float s_h[RPB][RPB];    // producer: corner history 'hist'; consumer: A matrix
    __shared__ float s_btc[RPB][RPB];  // consumer: B~ corner

    for (int c = 0; c < NB; c++) {
        const int k0 = c * RPB;

        // gather this block's rows at the chunk columns (chunk-start values)
        if (tid >= k0 && tid < k0 + RPB) {
            int col = tid - k0;
#pragma unroll
            for (int r = 0; r < RPB; r++) s_c0[r][col] = f[r];
        }
        __syncthreads();

        if (c == b) {
            // ---- PRODUCER ----
            // corner evolution on the 8x8 chunk-diagonal block (lane r owns corner row r):
            // records hist[r][m] = value of element (r,m) at the start of step m.
            if (tid < 8) {
                float cur[RPB], hist[RPB];
#pragma unroll
                for (int k = 0; k < RPB; k++) cur[k] = s_c0[tid][k];
#pragma unroll
                for (int m = 0; m < RPB; m++) {
                    hist[m] = cur[m];                       // pre-step col-m value
                    float rowm[RPB];
#pragma unroll
                    for (int cc = 0; cc < RPB; cc++)
                        rowm[cc] = __shfl_sync(0xFFu, cur[cc], m);  // row m (pre-step)
                    float cm = cur[m] * CINV;
#pragma unroll
                    for (int cc = 0; cc < RPB; cc++)
                        cur[cc] = fmaf(cm, rowm[cc], cur[cc]);      // simultaneous update
                }
#pragma unroll
                for (int m = 0; m < RPB; m++) s_h[tid][m] = hist[m];
            }
            __syncthreads();

            // B~ transform (per thread, depth-8 chain in registers):
            // B~[k] = CINV * ( f[k] + sum_{m<k} hist[k][m] * B~[m] )
            float Bt[RPB];
#pragma unroll
            for (int k = 0; k < RPB; k++) {
                float acc = f[k];
#pragma unroll
                for (int m = 0; m < RPB; m++)
                    if (m < k) acc = fmaf(s_h[k][m], Bt[m], acc);
                Bt[k] = acc * CINV;
                g_B[(k0 + k) * NMAT + tid] = Bt[k];
            }
            __threadfence();
            __syncthreads();
            if (tid == 0) st_rel_u(&g_flag[c], 1u);     // publish ASAP (own update after)

            // own rows final: f[r] += sum_k hist[r][k] * B~[k]
#pragma unroll
            for (int r = 0; r < RPB; r++) {
                float acc = f[r];
#pragma unroll
                for (int k = 0; k < RPB; k++) acc = fmaf(s_h[r][k], Bt[k], acc);
                f[r] = acc;
            }
        } else {
            // ---- CONSUMER ----
            if (tid == 0) { while (ld_acq_u(&g_flag[c]) == 0u) { } }
            __syncthreads();   // flag acquire + bar orders the B loads below

            float Bt[RPB];
#pragma unroll
            for (int k = 0; k < RPB; k++) Bt[k] = __ldcg(&g_B[(k0 + k) * NMAT + tid]);

            // stash B~ corner (columns k0..k0+7) to smem
            if (tid >= k0 && tid < k0 + RPB) {
                int cc = tid - k0;
#pragma unroll
                for (int m = 0; m < RPB; m++) s_btc[m][cc] = Bt[m];
            }
            __syncthreads();

            // A solve (lane r): a[r][k] = c0[r][k] + sum_{m<k} a[r][m] * B~c[m][k]
            if (tid < 8) {
                float a[RPB];
#pragma unroll
                for (int k = 0; k < RPB; k++) {
                    float acc = s_c0[tid][k];
#pragma unroll
                    for (int m = 0; m < RPB; m++)
                        if (m < k) acc = fmaf(a[m], s_btc[m][k], acc);
                    a[k] = acc;
                }
#pragma unroll
                for (int k = 0; k < RPB; k++) s_h[tid][k] = a[k];
            }
            __syncthreads();

            // rank-8 update: f[r] += sum_k A[r][k] * B~[k]
#pragma unroll
            for (int r = 0; r < RPB; r++) {
                float acc = f[r];
#pragma unroll
                for (int k = 0; k < RPB; k++) acc = fmaf(s_h[r][k], Bt[k], acc);
                f[r] = acc;
            }
        }
    }

    // ---- fused elementwise loss + reduction over this block's 8 rows (F in regs)
    double s_cost = 0.0, s_util = 0.0, s_ent = 0.0, s_mask = 0.0;
#pragma unroll
    for (int r = 0; r < RPB; r++) {
        int idx = (base + r) * NMAT + tid;
        float s  = sa[idx];
        float d  = dist[idx];
        float fl = flow[idx];
        float o  = oa[idx];

        s_cost += (double)(s * d);
        float eye = (base + r == tid) ? 1.0f : 0.0f;
        float t   = s * (eye - s);
        s_ent  += (double)(t * t);
        s_mask += (double)(s * (1.0f - o));

        float F  = f[r];
        float sp = (F > 1e-37f) ? fmaf(-0.1f, __logf(F), 4.0f) : 1.0e6f;  // w = 4 - 0.1*lnF
        float rail   = __expf(-0.005f * sp);
        float bas    = __expf(-0.01f  * d);
        float choice = rail / (rail + bas);
        float saved  = fmaf(-0.5f, sp, d);
        float u      = fl * choice * saved;
        float elu    = (u > 0.0f) ? u : expm1f(u);
        s_util += (double)(elu + 1.0f);
    }

    const unsigned FULL = 0xffffffffu;
#pragma unroll
    for (int off = 16; off > 0; off >>= 1) {
        s_cost += __shfl_down_sync(FULL, s_cost, off);
        s_util += __shfl_down_sync(FULL, s_util, off);
        s_ent  += __shfl_down_sync(FULL, s_ent , off);
        s_mask += __shfl_down_sync(FULL, s_mask, off);
    }
    __shared__ double red[16][4];
    int wid = tid >> 5, lid = tid & 31;
    if (lid == 0) { red[wid][0]=s_cost; red[wid][1]=s_util; red[wid][2]=s_ent; red[wid][3]=s_mask; }
    __syncthreads();
    if (tid == 0) {
        double a0=0, a1=0, a2=0, a3=0;
#pragma unroll
        for (int w = 0; w < 16; w++) { a0+=red[w][0]; a1+=red[w][1]; a2+=red[w][2]; a3+=red[w][3]; }
        g_part[b*4+0]=a0; g_part[b*4+1]=a1; g_part[b*4+2]=a2; g_part[b*4+3]=a3;
    }
}

// ---------------- final: sum 64 partials, apply entropy scale, write scalar
__global__ void final_kernel(const int* __restrict__ epoch_p, float* __restrict__ out) {
    int t = threadIdx.x;   // 32 threads
    double c0 = g_part[t*4+0] + g_part[(t+32)*4+0];
    double c1 = g_part[t*4+1] + g_part[(t+32)*4+1];
    double c2 = g_part[t*4+2] + g_part[(t+32)*4+2];
    double c3 = g_part[t*4+3] + g_part[(t+32)*4+3];
    const unsigned FULL = 0xffffffffu;
#pragma unroll
    for (int off = 16; off > 0; off >>= 1) {
        c0 += __shfl_down_sync(FULL, c0, off);
        c1 += __shfl_down_sync(FULL, c1, off);
        c2 += __shfl_down_sync(FULL, c2, off);
        c3 += __shfl_down_sync(FULL, c3, off);
    }
    if (t == 0) {
        int e = *epoch_p;
        double es = (e >= 50) ? 1.0 : (e >= 10) ? 0.1 : (e >= 0) ? 0.05 : 0.0;
        out[0] = (float)(c0 + c1 + c2 * es + 10000.0 * c3);
    }
}

extern "C" void kernel_launch(void* const* d_in, const int* in_sizes, int n_in,
                              void* d_out, int out_size) {
    const float* sa   = (const float*)d_in[0];
    const float* oa   = (const float*)d_in[1];
    const float* dist = (const float*)d_in[2];
    const float* flow = (const float*)d_in[3];
    const int*   ep   = (const int*)  d_in[4];

    init_kernel<<<N2 / 512, 512>>>(sa, dist);
    fw_kernel<<<NB, NMAT>>>(sa, oa, dist, flow);
    final_kernel<<<1, 32>>>(ep, (float*)d_out);
}